// round 2
// baseline (speedup 1.0000x reference)
#include <cuda_runtime.h>

#define S    512
#define C    192
#define B    2
#define BW   21
#define HALF 10
#define KS   7

// Scratch (allocation-free rule: __device__ globals)
__device__ float g_conv[B * C * S];   // band after depthwise conv
__device__ float g_attn[B * C * S];   // after pointwise + softmax

// ---------------------------------------------------------------------------
// K1: per (b,c) plane — gather diagonal stripe, band mean, depthwise conv k=7
// ---------------------------------------------------------------------------
__global__ void band_conv_kernel(const float* __restrict__ x,
                                 const float* __restrict__ conv_w) {
    __shared__ float stripe[S * BW];   // stripe[r*21 + k] = x[r, r-10+k] (0 OOB)
    __shared__ float band[S];

    const int bc  = blockIdx.x;                   // b*C + c
    const int c   = bc % C;
    const int tid = threadIdx.x;                  // 0..511
    const float* plane = x + ((size_t)bc << 18);  // bc * S*S

    // Phase 1: load stripe. Flat index -> contiguous runs of 21 per row.
    for (int idx = tid; idx < S * BW; idx += blockDim.x) {
        const int r   = idx / BW;
        const int k   = idx - r * BW;
        const int col = r - HALF + k;
        float v = 0.f;
        if (col >= 0 && col < S) v = __ldg(plane + r * S + col);
        stripe[idx] = v;
    }
    __syncthreads();

    // Phase 2: band[j] = mean over t of x[j-10+t, j] = stripe[(j-10+t)*21 + (20-t)]
    {
        const int j = tid;
        float sum = 0.f;
        #pragma unroll
        for (int t = 0; t < BW; t++) {
            const int r = j - HALF + t;
            if (r >= 0 && r < S) sum += stripe[r * BW + (BW - 1 - t)];
        }
        band[j] = sum * (1.0f / (float)BW);
    }
    __syncthreads();

    // Phase 3: depthwise conv1d, k=7, pad=3 (cross-correlation, per channel)
    {
        const int j = tid;
        float w[KS];
        #pragma unroll
        for (int k = 0; k < KS; k++) w[k] = __ldg(conv_w + c * KS + k);
        float acc = 0.f;
        #pragma unroll
        for (int k = 0; k < KS; k++) {
            const int s = j + k - 3;
            if (s >= 0 && s < S) acc += band[s] * w[k];
        }
        g_conv[bc * S + j] = acc;
    }
}

// ---------------------------------------------------------------------------
// K2: per (b,d) — pointwise 1x1 conv (GEMV over C) + bias + softmax over S
// ---------------------------------------------------------------------------
__global__ void point_softmax_kernel(const float* __restrict__ point_w,
                                     const float* __restrict__ point_b) {
    __shared__ float wrow[C];
    __shared__ float red[S];

    const int bd = blockIdx.x;         // b*C + d
    const int b  = bd / C;
    const int d  = bd - b * C;
    const int s  = threadIdx.x;        // 0..511

    if (s < C) wrow[s] = point_w[d * C + s];
    __syncthreads();

    const float* cb = g_conv + b * C * S;
    float acc = point_b[d];
    #pragma unroll 4
    for (int c = 0; c < C; c++)
        acc += cb[c * S + s] * wrow[c];

    // softmax over 512 values in the block
    red[s] = acc;
    __syncthreads();
    #pragma unroll
    for (int off = 256; off > 0; off >>= 1) {
        if (s < off) red[s] = fmaxf(red[s], red[s + off]);
        __syncthreads();
    }
    const float m = red[0];
    __syncthreads();

    const float e = __expf(acc - m);
    red[s] = e;
    __syncthreads();
    #pragma unroll
    for (int off = 256; off > 0; off >>= 1) {
        if (s < off) red[s] += red[s + off];
        __syncthreads();
    }
    const float inv = 1.0f / red[0];

    g_attn[bd * S + s] = e * inv;
}

// ---------------------------------------------------------------------------
// K3 (fixup): scale only the main-diagonal elements of out by attn.
// 384 blocks x 512 threads, one scattered element each (~13 MB sector traffic).
// ---------------------------------------------------------------------------
__global__ void diag_fixup_kernel(const float* __restrict__ x,
                                  float* __restrict__ out) {
    const int plane = blockIdx.x;           // b*C + c  (0..383)
    const int j     = threadIdx.x;          // 0..511
    const size_t addr = ((size_t)plane << 18) + (size_t)j * (S + 1);
    out[addr] = x[addr] * g_attn[(plane << 9) + j];
}

// ---------------------------------------------------------------------------
extern "C" void kernel_launch(void* const* d_in, const int* in_sizes, int n_in,
                              void* d_out, int out_size) {
    const float* x       = (const float*)d_in[0];   // [2,192,512,512]
    const float* conv_w  = (const float*)d_in[1];   // [192,1,7]
    const float* point_w = (const float*)d_in[2];   // [192,192]
    const float* point_b = (const float*)d_in[3];   // [192]
    float* out = (float*)d_out;

    // Bulk copy x -> out via the driver's tuned D2D path (graph-capturable).
    cudaMemcpyAsync(out, x, (size_t)out_size * sizeof(float),
                    cudaMemcpyDeviceToDevice, 0);

    band_conv_kernel<<<B * C, S>>>(x, conv_w);
    point_softmax_kernel<<<B * C, S>>>(point_w, point_b);

    // After both the copy and attn are done, patch the 196,608 diagonal elems.
    diag_fixup_kernel<<<B * C, S>>>(x, out);
}

// round 3
// speedup vs baseline: 1.1139x; 1.1139x over previous
#include <cuda_runtime.h>

#define S    512
#define C    192
#define B    2
#define BW   21
#define HALF 10
#define KS   7

// Scratch (allocation-free rule: __device__ globals)
__device__ float g_conv[B * C * S];   // band after depthwise conv
__device__ float g_attn[B * C * S];   // after pointwise + softmax

// ---------------------------------------------------------------------------
// K1: per (b,c) plane — gather diagonal stripe, band mean, depthwise conv k=7
// Phase 1 is a fully unrolled 21-load batch per thread (MLP=21) with
// division-free index stepping: idx += 512  =>  r += 24, k += 8 (mod 21).
// ---------------------------------------------------------------------------
__global__ void band_conv_kernel(const float* __restrict__ x,
                                 const float* __restrict__ conv_w) {
    __shared__ float stripe[S * BW];   // stripe[r*21 + k] = x[r, r-10+k] (0 OOB)
    __shared__ float band[S];

    const int bc  = blockIdx.x;                   // b*C + c
    const int c   = bc % C;
    const int tid = threadIdx.x;                  // 0..511
    const float* plane = x + ((size_t)bc << 18);  // bc * S*S

    // Phase 1: S*BW = 10752 = 21 * 512 exactly.
    {
        float v[21];
        int r = tid / BW;
        int k = tid - r * BW;
        int rr[21], kk[21];
        #pragma unroll
        for (int i = 0; i < 21; i++) {
            rr[i] = r; kk[i] = k;
            const int col = r - HALF + k;
            v[i] = (col >= 0 && col < S) ? plane[r * S + col] : 0.f;
            // idx += 512  ->  r += 24, k += 8, renormalize
            r += 24; k += 8;
            if (k >= BW) { k -= BW; r += 1; }
        }
        #pragma unroll
        for (int i = 0; i < 21; i++)
            stripe[rr[i] * BW + kk[i]] = v[i];
    }
    __syncthreads();

    // Phase 2: band[j] = mean over t of x[j-10+t, j] = stripe[(j-10+t)*21 + (20-t)]
    {
        const int j = tid;
        float sum = 0.f;
        #pragma unroll
        for (int t = 0; t < BW; t++) {
            const int r2 = j - HALF + t;
            if (r2 >= 0 && r2 < S) sum += stripe[r2 * BW + (BW - 1 - t)];
        }
        band[j] = sum * (1.0f / (float)BW);
    }
    __syncthreads();

    // Phase 3: depthwise conv1d, k=7, pad=3 (cross-correlation, per channel)
    {
        const int j = tid;
        float w[KS];
        #pragma unroll
        for (int k2 = 0; k2 < KS; k2++) w[k2] = conv_w[c * KS + k2];
        float acc = 0.f;
        #pragma unroll
        for (int k2 = 0; k2 < KS; k2++) {
            const int s = j + k2 - 3;
            if (s >= 0 && s < S) acc += band[s] * w[k2];
        }
        g_conv[bc * S + j] = acc;
    }
}

// ---------------------------------------------------------------------------
// K2: per (b,d) — pointwise 1x1 conv (GEMV over C) + bias + softmax over S
// ---------------------------------------------------------------------------
__global__ void point_softmax_kernel(const float* __restrict__ point_w,
                                     const float* __restrict__ point_b) {
    __shared__ float wrow[C];
    __shared__ float red[S];

    const int bd = blockIdx.x;         // b*C + d
    const int b  = bd / C;
    const int d  = bd - b * C;
    const int s  = threadIdx.x;        // 0..511

    if (s < C) wrow[s] = point_w[d * C + s];
    __syncthreads();

    const float* cb = g_conv + b * C * S;
    float acc = point_b[d];
    #pragma unroll 4
    for (int c = 0; c < C; c++)
        acc += cb[c * S + s] * wrow[c];

    // softmax over 512 values in the block
    red[s] = acc;
    __syncthreads();
    #pragma unroll
    for (int off = 256; off > 0; off >>= 1) {
        if (s < off) red[s] = fmaxf(red[s], red[s + off]);
        __syncthreads();
    }
    const float m = red[0];
    __syncthreads();

    const float e = __expf(acc - m);
    red[s] = e;
    __syncthreads();
    #pragma unroll
    for (int off = 256; off > 0; off >>= 1) {
        if (s < off) red[s] += red[s + off];
        __syncthreads();
    }
    const float inv = 1.0f / red[0];

    g_attn[bd * S + s] = e * inv;
}

// ---------------------------------------------------------------------------
// K3: streaming copy x -> out (4 x float4 per thread, block-strided so every
// access is a full 128B line), scaling the main diagonal by attn.
// Streaming cache hints; loads batched before stores (MLP=4).
// ---------------------------------------------------------------------------
__global__ void __launch_bounds__(256) copy_diag_kernel(
        const float4* __restrict__ x4, float4* __restrict__ out4) {
    const int tid  = threadIdx.x;
    const int base = blockIdx.x * 1024 + tid;

    float4 val[4];
    #pragma unroll
    for (int i = 0; i < 4; i++)
        val[i] = __ldcs(x4 + base + i * 256);

    #pragma unroll
    for (int i = 0; i < 4; i++) {
        const int v     = base + i * 256;
        const int e     = v << 2;          // element index (< 2^27)
        const int j0    = e & (S - 1);     // column of lane 0
        const int r     = (e >> 9) & (S - 1);
        const int plane = e >> 18;         // b*C + c
        const int dr    = r - j0;

        if ((unsigned)dr < 4u) {
            const float a = g_attn[(plane << 9) + r];
            if      (dr == 0) val[i].x *= a;
            else if (dr == 1) val[i].y *= a;
            else if (dr == 2) val[i].z *= a;
            else              val[i].w *= a;
        }
        __stcs(out4 + v, val[i]);
    }
}

// ---------------------------------------------------------------------------
extern "C" void kernel_launch(void* const* d_in, const int* in_sizes, int n_in,
                              void* d_out, int out_size) {
    const float* x       = (const float*)d_in[0];   // [2,192,512,512]
    const float* conv_w  = (const float*)d_in[1];   // [192,1,7]
    const float* point_w = (const float*)d_in[2];   // [192,192]
    const float* point_b = (const float*)d_in[3];   // [192]
    float* out = (float*)d_out;

    band_conv_kernel<<<B * C, S>>>(x, conv_w);
    point_softmax_kernel<<<B * C, S>>>(point_w, point_b);

    const int n4     = out_size >> 2;     // 25,165,824 float4 (divisible by 1024)
    const int blocks = n4 >> 10;          // 24576 blocks, no tail
    copy_diag_kernel<<<blocks, 256>>>((const float4*)x, (float4*)out);
}